// round 2
// baseline (speedup 1.0000x reference)
#include <cuda_runtime.h>
#include <cstddef>

#define BB 4
#define NN 4096
#define KK 16
#define DP 64
#define DM 256
#define NPTS (BB*NN)

// ---------------- device-global scratch (no allocs allowed) ----------------
__device__ float g_WpreT[DP*DM];
__device__ float g_WQT  [DM*DM];
__device__ float g_WKT  [DM*DM];
__device__ float g_WVT  [DM*DM];
__device__ float g_Wp2T [DM*DM];
__device__ float g_Wa1T [DM*DM];
__device__ float g_Wa2T [DM*DM];
__device__ float g_WprojT[DM*DM];
__device__ float g_WpostT[DM*DP];
__device__ float g_Q [NPTS*DM];
__device__ float g_Kf[NPTS*DM];
__device__ float g_Vf[NPTS*DM];
__device__ int   g_idx[NPTS*KK];

// ---------------- weight transposes (coalesced gemv reads) ----------------
__global__ void prep_kernel(const float* __restrict__ W_pre,
                            const float* __restrict__ WQ,  const float* __restrict__ WK,
                            const float* __restrict__ WV,  const float* __restrict__ Wp2,
                            const float* __restrict__ Wa1, const float* __restrict__ Wa2,
                            const float* __restrict__ Wproj, const float* __restrict__ W_post)
{
    int t = blockIdx.x * blockDim.x + threadIdx.x;
    if (t < DM*DP) {                       // W_pre: [256][64] -> WpreT[j][f]
        int fo = t >> 6, j = t & 63;
        g_WpreT[j*DM + fo] = W_pre[t];
    }
    if (t < DP*DM) {                       // W_post: [64][256] -> WpostT[j][p]
        int p = t >> 8, j = t & 255;
        g_WpostT[j*DP + p] = W_post[t];
    }
    if (t < DM*DM) {
        int r = t >> 8, c = t & 255;
        g_WQT   [c*DM + r] = WQ[t];
        g_WKT   [c*DM + r] = WK[t];
        g_WVT   [c*DM + r] = WV[t];
        g_Wp2T  [c*DM + r] = Wp2[t];
        g_Wa1T  [c*DM + r] = Wa1[t];
        g_Wa2T  [c*DM + r] = Wa2[t];
        g_WprojT[c*DM + r] = Wproj[t];
    }
}

// ---------------- kNN: per-batch xyz in smem, worst-replace top-16 ----------------
__global__ void __launch_bounds__(256) knn_kernel(const float* __restrict__ xyz)
{
    extern __shared__ float4 pts[];        // 4096 * 16B = 64 KB
    int b     = blockIdx.x >> 4;           // NN/256 = 16 chunks per batch
    int chunk = blockIdx.x & 15;
    const float* xb = xyz + (size_t)b * NN * 3;
    for (int m = threadIdx.x; m < NN; m += 256)
        pts[m] = make_float4(xb[m*3], xb[m*3+1], xb[m*3+2], 0.f);
    __syncthreads();

    int qi = chunk * 256 + threadIdx.x;
    float4 qp = pts[qi];

    float bd[KK]; int bi[KK];
    #pragma unroll
    for (int i = 0; i < KK; i++) { bd[i] = 3.4e38f; bi[i] = i; }
    float worst = 3.4e38f; int wpos = 0;

    for (int m = 0; m < NN; m++) {
        float4 p = pts[m];
        float dx = qp.x - p.x, dy = qp.y - p.y, dz = qp.z - p.z;
        float d = fmaf(dx, dx, fmaf(dy, dy, dz * dz));
        if (d < worst) {
            bd[wpos] = d; bi[wpos] = m;
            worst = bd[0]; wpos = 0;
            #pragma unroll
            for (int i = 1; i < KK; i++)
                if (bd[i] > worst) { worst = bd[i]; wpos = i; }
        }
    }
    #pragma unroll
    for (int i = 0; i < KK; i++)
        g_idx[(size_t)(b*NN + qi)*KK + i] = bi[i];
}

// ---------------- register-blocked gemv: 1 weight load -> 16 FMAs ----------------
template<int LEN>
__device__ __forceinline__ void gemv16(const float* __restrict__ WT,
                                       const float* __restrict__ hb,
                                       int f, float* acc)
{
    #pragma unroll 4
    for (int j = 0; j < LEN; j++) {
        float w = __ldg(&WT[j*DM + f]);
        const float4* hr = reinterpret_cast<const float4*>(hb + j*20);
        float4 h0 = hr[0], h1 = hr[1], h2 = hr[2], h3 = hr[3];
        acc[0]  = fmaf(w, h0.x, acc[0]);  acc[1]  = fmaf(w, h0.y, acc[1]);
        acc[2]  = fmaf(w, h0.z, acc[2]);  acc[3]  = fmaf(w, h0.w, acc[3]);
        acc[4]  = fmaf(w, h1.x, acc[4]);  acc[5]  = fmaf(w, h1.y, acc[5]);
        acc[6]  = fmaf(w, h1.z, acc[6]);  acc[7]  = fmaf(w, h1.w, acc[7]);
        acc[8]  = fmaf(w, h2.x, acc[8]);  acc[9]  = fmaf(w, h2.y, acc[9]);
        acc[10] = fmaf(w, h2.z, acc[10]); acc[11] = fmaf(w, h2.w, acc[11]);
        acc[12] = fmaf(w, h3.x, acc[12]); acc[13] = fmaf(w, h3.y, acc[13]);
        acc[14] = fmaf(w, h3.z, acc[14]); acc[15] = fmaf(w, h3.w, acc[15]);
    }
}

__device__ __forceinline__ void warp_bfly2(float& s, float& s2)
{
    #pragma unroll
    for (int o = 16; o; o >>= 1) {
        s  += __shfl_xor_sync(0xffffffffu, s , o);
        s2 += __shfl_xor_sync(0xffffffffu, s2, o);
    }
}

// block-wide sum of two values; trailing state ready for reuse of `red`
__device__ __forceinline__ float2 block_sum2(float s, float s2, float* red, int f)
{
    warp_bfly2(s, s2);
    int w = f >> 5;
    __syncthreads();                        // protect red from previous use
    if ((f & 31) == 0) { red[w] = s; red[8 + w] = s2; }
    __syncthreads();
    float ts = 0.f, t2 = 0.f;
    #pragma unroll
    for (int i = 0; i < 8; i++) { ts += red[i]; t2 += red[8 + i]; }
    return make_float2(ts, t2);
}

// ---------------- QKV precompute: 16 points per block, LN fused ----------------
__device__ __forceinline__ void qkv_proj(const float* __restrict__ WT,
    const float* __restrict__ ibuf, float* obuf,
    const float* __restrict__ gg, const float* __restrict__ bb,
    float* __restrict__ outg, int f)
{
    float acc[16];
    #pragma unroll
    for (int k = 0; k < 16; k++) acc[k] = 0.f;
    gemv16<DM>(WT, ibuf, f, acc);
    #pragma unroll
    for (int k = 0; k < 16; k++) obuf[k*260 + f] = acc[k];
    __syncthreads();

    int wid = f >> 5, lane = f & 31;        // warp w normalizes points 2w, 2w+1
    #pragma unroll
    for (int pp = 0; pp < 2; pp++) {
        int p = wid*2 + pp;
        const float* row = &obuf[p*260];
        float v[8]; float s = 0.f, s2 = 0.f;
        #pragma unroll
        for (int i = 0; i < 8; i++) { float x = row[lane*8 + i]; v[i] = x; s += x; s2 += x*x; }
        warp_bfly2(s, s2);
        float mu  = s  * (1.f/DM);
        float var = s2 * (1.f/DM) - mu*mu;
        float rs  = rsqrtf(var + 1e-5f);
        #pragma unroll
        for (int i = 0; i < 8; i++) {
            int c = lane*8 + i;
            outg[(size_t)p*DM + c] = (v[i] - mu) * rs * gg[c] + bb[c];
        }
    }
    __syncthreads();                        // obuf reusable
}

__global__ void __launch_bounds__(256) qkv_kernel(
    const float* __restrict__ features, const float* __restrict__ b_pre,
    const float* __restrict__ gdm, const float* __restrict__ bdm)
{
    int p0 = blockIdx.x * 16;
    int f  = threadIdx.x;
    __shared__ __align__(16) float featsm[DP*20];
    __shared__ __align__(16) float ibuf  [DM*20];
    __shared__ float obuf[16*260];

    for (int t = f; t < 16*DP; t += 256) {
        int p = t >> 6, j = t & 63;
        featsm[j*20 + p] = features[(size_t)(p0 + p)*DP + j];
    }
    __syncthreads();

    float acc[16];
    float bp = b_pre[f];
    #pragma unroll
    for (int k = 0; k < 16; k++) acc[k] = bp;
    gemv16<DP>(g_WpreT, featsm, f, acc);
    #pragma unroll
    for (int k = 0; k < 16; k++) ibuf[f*20 + k] = acc[k];
    __syncthreads();

    qkv_proj(g_WQT, ibuf, obuf, gdm, bdm, g_Q  + (size_t)p0*DM, f);
    qkv_proj(g_WKT, ibuf, obuf, gdm, bdm, g_Kf + (size_t)p0*DM, f);
    qkv_proj(g_WVT, ibuf, obuf, gdm, bdm, g_Vf + (size_t)p0*DM, f);
}

// ---------------- fused per-point attention block ----------------
__global__ void __launch_bounds__(256) main_kernel(
    const float* __restrict__ xyz, const float* __restrict__ features,
    const float* __restrict__ Wp1, const float* __restrict__ b_post,
    const float* __restrict__ gdm, const float* __restrict__ bdm,
    const float* __restrict__ gdp, const float* __restrict__ bdp,
    float* __restrict__ out)
{
    int pt = blockIdx.x;
    int b  = pt >> 12, n = pt & (NN - 1);
    int f  = threadIdx.x;

    __shared__ __align__(16) float hbuf[DM*20];   // staged [j][k], stride 20 (bank-clean)
    __shared__ float relbuf[KK*4];
    __shared__ int   idxs[KK];
    __shared__ float resbuf[DM];
    __shared__ float red[16];

    if (f < KK) {
        int id = g_idx[(size_t)pt*KK + f];
        idxs[f] = id;
        const float* xb = xyz + (size_t)b*NN*3;
        relbuf[f*4 + 0] = xb[n*3 + 0] - xb[id*3 + 0];
        relbuf[f*4 + 1] = xb[n*3 + 1] - xb[id*3 + 1];
        relbuf[f*4 + 2] = xb[n*3 + 2] - xb[id*3 + 2];
    }
    float qf = g_Q[(size_t)pt*DM + f];
    float w0 = Wp1[f*3 + 0], w1 = Wp1[f*3 + 1], w2 = Wp1[f*3 + 2];
    __syncthreads();

    // h1 = relu(rel @ Wp1^T): stage into hbuf[j][k]
    #pragma unroll
    for (int k = 0; k < KK; k++) {
        float h = fmaf(w0, relbuf[k*4+0], fmaf(w1, relbuf[k*4+1], w2*relbuf[k*4+2]));
        hbuf[f*20 + k] = fmaxf(h, 0.f);
    }
    __syncthreads();

    // pos = h1 @ Wp2^T  (16 neighbors in registers)
    float acc[KK];
    #pragma unroll
    for (int k = 0; k < KK; k++) acc[k] = 0.f;
    gemv16<DM>(g_Wp2T, hbuf, f, acc);
    __syncthreads();                               // everyone done reading h1

    float pos[KK], U[KK];
    #pragma unroll
    for (int k = 0; k < KK; k++) pos[k] = acc[k];

    // gather K/V, build t = q - k + pos into hbuf; U = v + pos stays in regs
    int bbase = b * NN;
    #pragma unroll
    for (int k = 0; k < KK; k++) {
        size_t off = (size_t)(bbase + idxs[k])*DM + f;
        float kv = g_Kf[off], vv = g_Vf[off];
        U[k] = vv + pos[k];
        hbuf[f*20 + k] = qf - kv + pos[k];
    }
    __syncthreads();

    // h2 = relu(t @ Wa1^T)
    #pragma unroll
    for (int k = 0; k < KK; k++) acc[k] = 0.f;
    gemv16<DM>(g_Wa1T, hbuf, f, acc);
    __syncthreads();
    #pragma unroll
    for (int k = 0; k < KK; k++) hbuf[f*20 + k] = fmaxf(acc[k], 0.f);
    __syncthreads();

    // A = h2 @ Wa2^T
    #pragma unroll
    for (int k = 0; k < KK; k++) acc[k] = 0.f;
    gemv16<DM>(g_Wa2T, hbuf, f, acc);

    // softmax over k (per feature, fully register-resident) + reduce
    float m = acc[0];
    #pragma unroll
    for (int k = 1; k < KK; k++) m = fmaxf(m, acc[k]);
    float ssum = 0.f, res = 0.f;
    #pragma unroll
    for (int k = 0; k < KK; k++) {
        float e = expf((acc[k] - m) * (1.0f/16.0f));  // 1/sqrt(256)
        ssum += e;
        res = fmaf(e, U[k], res);
    }
    res /= ssum;
    resbuf[f] = res;
    __syncthreads();

    // proj + LN(256)
    float y = 0.f;
    #pragma unroll 4
    for (int j = 0; j < DM; j++) y = fmaf(__ldg(&g_WprojT[j*DM + f]), resbuf[j], y);
    float2 ss = block_sum2(y, y*y, red, f);
    float mu  = ss.x * (1.f/DM);
    float var = ss.y * (1.f/DM) - mu*mu;
    float z   = (y - mu) * rsqrtf(var + 1e-5f) * gdm[f] + bdm[f];
    __syncthreads();
    resbuf[f] = z;
    __syncthreads();

    // post (64 out) + LN(64) + residual
    float o = 0.f;
    if (f < DP) {
        o = b_post[f];
        #pragma unroll 4
        for (int j = 0; j < DM; j++) o = fmaf(__ldg(&g_WpostT[j*DP + f]), resbuf[j], o);
    }
    float2 so = block_sum2((f < DP) ? o : 0.f, (f < DP) ? o*o : 0.f, red, f);
    if (f < DP) {
        float mu2  = so.x * (1.f/DP);
        float var2 = so.y * (1.f/DP) - mu2*mu2;
        float ov = (o - mu2) * rsqrtf(var2 + 1e-5f) * gdp[f] + bdp[f]
                 + features[(size_t)pt*DP + f];
        out[(size_t)pt*DP + f] = ov;
    }
}

// ---------------- launch ----------------
extern "C" void kernel_launch(void* const* d_in, const int* in_sizes, int n_in,
                              void* d_out, int out_size)
{
    const float* xyz      = (const float*)d_in[0];
    const float* features = (const float*)d_in[1];
    const float* W_pre    = (const float*)d_in[2];
    const float* b_pre    = (const float*)d_in[3];
    const float* W_post   = (const float*)d_in[4];
    const float* b_post   = (const float*)d_in[5];
    const float* Wp1      = (const float*)d_in[6];
    const float* Wp2      = (const float*)d_in[7];
    const float* Wa1      = (const float*)d_in[8];
    const float* Wa2      = (const float*)d_in[9];
    const float* WQ       = (const float*)d_in[10];
    const float* WK       = (const float*)d_in[11];
    const float* WV       = (const float*)d_in[12];
    const float* Wproj    = (const float*)d_in[13];
    const float* g_dm     = (const float*)d_in[14];
    const float* b_dm     = (const float*)d_in[15];
    const float* g_dp     = (const float*)d_in[16];
    const float* b_dp     = (const float*)d_in[17];
    float* out = (float*)d_out;

    cudaFuncSetAttribute(knn_kernel, cudaFuncAttributeMaxDynamicSharedMemorySize,
                         NN * (int)sizeof(float4));

    prep_kernel<<<256, 256>>>(W_pre, WQ, WK, WV, Wp2, Wa1, Wa2, Wproj, W_post);
    knn_kernel<<<BB*(NN/256), 256, NN*sizeof(float4)>>>(xyz);
    qkv_kernel<<<NPTS/16, 256>>>(features, b_pre, g_dm, b_dm);
    main_kernel<<<NPTS, 256>>>(xyz, features, Wp1, b_post, g_dm, b_dm, g_dp, b_dp, out);
}

// round 4
// speedup vs baseline: 2.3941x; 2.3941x over previous
#include <cuda_runtime.h>
#include <cstddef>
#include <cstdint>

#define BB 4
#define NN 4096
#define KK 16
#define DP 64
#define DM 256
#define NPTS (BB*NN)
#define MTOT (NPTS*KK)          // 262144 rows for the big GEMMs

// ---------------- device-global scratch (no allocs allowed) ----------------
__device__ float g_WpreT[DP*DM];
__device__ float g_WQT  [DM*DM];
__device__ float g_WKT  [DM*DM];
__device__ float g_WVT  [DM*DM];
__device__ float g_WprojT[DM*DM];
__device__ float g_WpostT[DM*DP];
__device__ float g_Wp2r [DM*DM];   // tf32-rounded, row-major [n][k]
__device__ float g_Wa1r [DM*DM];
__device__ float g_Wa2r [DM*DM];
__device__ float g_Q [NPTS*DM];
__device__ float g_Kf[NPTS*DM];
__device__ float g_Vf[NPTS*DM];
__device__ int   g_idx[NPTS*KK];
__device__ float g_h1[(size_t)MTOT*DM];   // h1, later reused as h2
__device__ float g_t [(size_t)MTOT*DM];
__device__ float g_U [(size_t)MTOT*DM];
__device__ float g_res[(size_t)NPTS*DM];

// ---------------- helpers ----------------
__device__ __forceinline__ uint32_t smem_u32(const void* p) {
    uint32_t a;
    asm("{ .reg .u64 t; cvta.to.shared.u64 t, %1; cvt.u32.u64 %0, t; }" : "=r"(a) : "l"(p));
    return a;
}
__device__ __forceinline__ float rna_tf32(float x) {
    uint32_t r;
    asm("cvt.rna.tf32.f32 %0, %1;" : "=r"(r) : "f"(x));
    return __uint_as_float(r);
}
#define CP16(dst, src) asm volatile("cp.async.cg.shared.global [%0], [%1], 16;" :: "r"(dst), "l"(src) : "memory")
#define CP_COMMIT()    asm volatile("cp.async.commit_group;" ::: "memory")
#define CP_WAIT1()     asm volatile("cp.async.wait_group 1;" ::: "memory")
#define LDSM4(r0,r1,r2,r3,a) \
    asm volatile("ldmatrix.sync.aligned.m8n8.x4.shared.b16 {%0,%1,%2,%3}, [%4];" \
                 : "=r"(r0),"=r"(r1),"=r"(r2),"=r"(r3) : "r"(a))

__device__ __forceinline__ void mma1688(float* c, const uint32_t* a, uint32_t b0, uint32_t b1) {
    asm volatile("mma.sync.aligned.m16n8k8.row.col.f32.tf32.tf32.f32 "
        "{%0,%1,%2,%3}, {%4,%5,%6,%7}, {%8,%9}, {%0,%1,%2,%3};"
        : "+f"(c[0]), "+f"(c[1]), "+f"(c[2]), "+f"(c[3])
        : "r"(a[0]), "r"(a[1]), "r"(a[2]), "r"(a[3]), "r"(b0), "r"(b1));
}

// ---------------- weight prep: transposes for SIMT paths + tf32 rounding ---------
__global__ void prep_kernel(const float* __restrict__ W_pre,
                            const float* __restrict__ WQ,  const float* __restrict__ WK,
                            const float* __restrict__ WV,  const float* __restrict__ Wproj,
                            const float* __restrict__ W_post,
                            const float* __restrict__ Wp2, const float* __restrict__ Wa1,
                            const float* __restrict__ Wa2)
{
    int t = blockIdx.x * blockDim.x + threadIdx.x;
    if (t < DM*DP) {                       // W_pre: [256][64]
        int fo = t >> 6, j = t & 63;
        g_WpreT[j*DM + fo] = W_pre[t];
    }
    if (t < DP*DM) {                       // W_post: [64][256]
        int p = t >> 8, j = t & 255;
        g_WpostT[j*DP + p] = W_post[t];
    }
    if (t < DM*DM) {
        int r = t >> 8, c = t & 255;
        g_WQT   [c*DM + r] = WQ[t];
        g_WKT   [c*DM + r] = WK[t];
        g_WVT   [c*DM + r] = WV[t];
        g_WprojT[c*DM + r] = Wproj[t];
        g_Wp2r[t] = rna_tf32(Wp2[t]);
        g_Wa1r[t] = rna_tf32(Wa1[t]);
        g_Wa2r[t] = rna_tf32(Wa2[t]);
    }
}

// ---------------- kNN ----------------
__global__ void __launch_bounds__(256) knn_kernel(const float* __restrict__ xyz)
{
    extern __shared__ float4 pts[];        // 4096 * 16B = 64 KB
    int b     = blockIdx.x >> 4;
    int chunk = blockIdx.x & 15;
    const float* xb = xyz + (size_t)b * NN * 3;
    for (int m = threadIdx.x; m < NN; m += 256)
        pts[m] = make_float4(xb[m*3], xb[m*3+1], xb[m*3+2], 0.f);
    __syncthreads();

    int qi = chunk * 256 + threadIdx.x;
    float4 qp = pts[qi];

    float bd[KK]; int bi[KK];
    #pragma unroll
    for (int i = 0; i < KK; i++) { bd[i] = 3.4e38f; bi[i] = i; }
    float worst = 3.4e38f; int wpos = 0;

    for (int m = 0; m < NN; m++) {
        float4 p = pts[m];
        float dx = qp.x - p.x, dy = qp.y - p.y, dz = qp.z - p.z;
        float d = fmaf(dx, dx, fmaf(dy, dy, dz * dz));
        if (d < worst) {
            bd[wpos] = d; bi[wpos] = m;
            worst = bd[0]; wpos = 0;
            #pragma unroll
            for (int i = 1; i < KK; i++)
                if (bd[i] > worst) { worst = bd[i]; wpos = i; }
        }
    }
    #pragma unroll
    for (int i = 0; i < KK; i++)
        g_idx[(size_t)(b*NN + qi)*KK + i] = bi[i];
}

// ---------------- SIMT gemv helpers (qkv + final) ----------------
template<int LEN>
__device__ __forceinline__ void gemv16(const float* __restrict__ WT,
                                       const float* __restrict__ hb,
                                       int f, float* acc)
{
    #pragma unroll 4
    for (int j = 0; j < LEN; j++) {
        float w = __ldg(&WT[j*DM + f]);
        const float4* hr = reinterpret_cast<const float4*>(hb + j*20);
        float4 h0 = hr[0], h1 = hr[1], h2 = hr[2], h3 = hr[3];
        acc[0]  = fmaf(w, h0.x, acc[0]);  acc[1]  = fmaf(w, h0.y, acc[1]);
        acc[2]  = fmaf(w, h0.z, acc[2]);  acc[3]  = fmaf(w, h0.w, acc[3]);
        acc[4]  = fmaf(w, h1.x, acc[4]);  acc[5]  = fmaf(w, h1.y, acc[5]);
        acc[6]  = fmaf(w, h1.z, acc[6]);  acc[7]  = fmaf(w, h1.w, acc[7]);
        acc[8]  = fmaf(w, h2.x, acc[8]);  acc[9]  = fmaf(w, h2.y, acc[9]);
        acc[10] = fmaf(w, h2.z, acc[10]); acc[11] = fmaf(w, h2.w, acc[11]);
        acc[12] = fmaf(w, h3.x, acc[12]); acc[13] = fmaf(w, h3.y, acc[13]);
        acc[14] = fmaf(w, h3.z, acc[14]); acc[15] = fmaf(w, h3.w, acc[15]);
    }
}

__device__ __forceinline__ void warp_bfly2(float& s, float& s2)
{
    #pragma unroll
    for (int o = 16; o; o >>= 1) {
        s  += __shfl_xor_sync(0xffffffffu, s , o);
        s2 += __shfl_xor_sync(0xffffffffu, s2, o);
    }
}

__device__ __forceinline__ void qkv_proj(const float* __restrict__ WT,
    const float* __restrict__ ibuf, float* obuf,
    const float* __restrict__ gg, const float* __restrict__ bb,
    float* __restrict__ outg, int f)
{
    float acc[16];
    #pragma unroll
    for (int k = 0; k < 16; k++) acc[k] = 0.f;
    gemv16<DM>(WT, ibuf, f, acc);
    #pragma unroll
    for (int k = 0; k < 16; k++) obuf[k*260 + f] = acc[k];
    __syncthreads();

    int wid = f >> 5, lane = f & 31;
    #pragma unroll
    for (int pp = 0; pp < 2; pp++) {
        int p = wid*2 + pp;
        const float* row = &obuf[p*260];
        float v[8]; float s = 0.f, s2 = 0.f;
        #pragma unroll
        for (int i = 0; i < 8; i++) { float x = row[lane*8 + i]; v[i] = x; s += x; s2 += x*x; }
        warp_bfly2(s, s2);
        float mu  = s  * (1.f/DM);
        float var = s2 * (1.f/DM) - mu*mu;
        float rs  = rsqrtf(var + 1e-5f);
        #pragma unroll
        for (int i = 0; i < 8; i++) {
            int c = lane*8 + i;
            outg[(size_t)p*DM + c] = (v[i] - mu) * rs * gg[c] + bb[c];
        }
    }
    __syncthreads();
}

__global__ void __launch_bounds__(256) qkv_kernel(
    const float* __restrict__ features, const float* __restrict__ b_pre,
    const float* __restrict__ gdm, const float* __restrict__ bdm)
{
    int p0 = blockIdx.x * 16;
    int f  = threadIdx.x;
    __shared__ __align__(16) float featsm[DP*20];
    __shared__ __align__(16) float ibuf  [DM*20];
    __shared__ float obuf[16*260];

    for (int t = f; t < 16*DP; t += 256) {
        int p = t >> 6, j = t & 63;
        featsm[j*20 + p] = features[(size_t)(p0 + p)*DP + j];
    }
    __syncthreads();

    float acc[16];
    float bp = b_pre[f];
    #pragma unroll
    for (int k = 0; k < 16; k++) acc[k] = bp;
    gemv16<DP>(g_WpreT, featsm, f, acc);
    #pragma unroll
    for (int k = 0; k < 16; k++) ibuf[f*20 + k] = acc[k];
    __syncthreads();

    qkv_proj(g_WQT, ibuf, obuf, gdm, bdm, g_Q  + (size_t)p0*DM, f);
    qkv_proj(g_WKT, ibuf, obuf, gdm, bdm, g_Kf + (size_t)p0*DM, f);
    qkv_proj(g_WVT, ibuf, obuf, gdm, bdm, g_Vf + (size_t)p0*DM, f);
}

// ---------------- h1 = relu(rel @ Wp1^T), tf32-rounded ----------------
__global__ void __launch_bounds__(256) h1_kernel(const float* __restrict__ xyz,
                                                 const float* __restrict__ Wp1)
{
    int pt = blockIdx.x;
    int b  = pt >> 12, n = pt & (NN - 1);
    int f  = threadIdx.x;
    __shared__ float relbuf[KK*4];

    if (f < KK) {
        int id = g_idx[(size_t)pt*KK + f];
        const float* xb = xyz + (size_t)b*NN*3;
        relbuf[f*4 + 0] = xb[n*3 + 0] - xb[id*3 + 0];
        relbuf[f*4 + 1] = xb[n*3 + 1] - xb[id*3 + 1];
        relbuf[f*4 + 2] = xb[n*3 + 2] - xb[id*3 + 2];
    }
    float w0 = Wp1[f*3 + 0], w1 = Wp1[f*3 + 1], w2 = Wp1[f*3 + 2];
    __syncthreads();

    #pragma unroll
    for (int k = 0; k < KK; k++) {
        float h = fmaf(w0, relbuf[k*4+0], fmaf(w1, relbuf[k*4+1], w2*relbuf[k*4+2]));
        g_h1[((size_t)pt*KK + k)*DM + f] = rna_tf32(fmaxf(h, 0.f));
    }
}

// ---------------- mma.sync tf32 GEMM, fused epilogues ----------------
// C[M=262144, N=256] = A @ W^T ; BM=128, BN=128 (grid.y=2), BK=32.
// 8 warps: wm = wid&3 (32 rows), wn = wid>>2 (64 cols). Warp tile 32x64.
// EPI 0: pos -> t = q - kgather + pos (rounded), U = vgather + pos
// EPI 1: h2 = relu(C) rounded -> g_h1
// EPI 2: softmax over the 16 rows of each point per column, reduce with U -> g_res
#define GPITCH 36                       // smem row pitch in floats (9 x 16B)
#define GBUF   (128*GPITCH)             // floats per A (or B) buffer
#define GBUFB  (GBUF*4)                 // bytes
#define GEMM_SMEM (4*GBUFB)             // A x2 + B x2 = 73728 B

template<int EPI>
__global__ void __launch_bounds__(256) gemm_kernel(const float* __restrict__ A,
                                                   const float* __restrict__ Bw)
{
    extern __shared__ float smem[];
    const int tid  = threadIdx.x;
    const int lane = tid & 31, wid = tid >> 5;
    const int wm   = wid & 3,  wn  = wid >> 2;
    const int m0   = blockIdx.x * 128;
    const int n0   = blockIdx.y * 128;

    uint32_t sA = smem_u32(smem);
    uint32_t sB = sA + 2*GBUFB;

    // ldmatrix per-thread base addresses (bytes)
    const int aRow = wm*32 + (lane & 7) + ((lane >> 3) & 1)*8;
    const uint32_t aAddr = sA + (uint32_t)aRow*144 + ((lane >> 4) & 1)*16;
    const int bRow = wn*64 + (lane & 7) + ((lane >> 4) & 1)*8;
    const uint32_t bAddr = sB + (uint32_t)bRow*144 + ((lane >> 3) & 1)*16;

    float acc[2][8][4];
    #pragma unroll
    for (int mt = 0; mt < 2; mt++)
        #pragma unroll
        for (int nt = 0; nt < 8; nt++)
            #pragma unroll
            for (int j = 0; j < 4; j++) acc[mt][nt][j] = 0.f;

    // tile loader: 128 rows x 32 floats each for A and B
    auto load_tile = [&](int kt, int buf) {
        #pragma unroll
        for (int i = 0; i < 4; i++) {
            int ch = tid + i*256;
            int r = ch >> 3, c = ch & 7;
            uint32_t off = (uint32_t)(buf*GBUFB + r*144 + c*16);
            CP16(sA + off, A  + (size_t)(m0 + r)*256 + kt*32 + c*4);
            CP16(sB + off, Bw + (size_t)(n0 + r)*256 + kt*32 + c*4);
        }
    };

    load_tile(0, 0); CP_COMMIT();
    load_tile(1, 1); CP_COMMIT();

    for (int kt = 0; kt < 8; kt++) {
        int buf = kt & 1;
        CP_WAIT1();
        __syncthreads();

        uint32_t ab = aAddr + buf*GBUFB;
        uint32_t bb = bAddr + buf*GBUFB;
        #pragma unroll
        for (int ks = 0; ks < 4; ks++) {
            uint32_t af[2][4], bf[4][4];
            LDSM4(af[0][0], af[0][1], af[0][2], af[0][3], ab + ks*32);
            LDSM4(af[1][0], af[1][1], af[1][2], af[1][3], ab + 2304 + ks*32);
            #pragma unroll
            for (int ntp = 0; ntp < 4; ntp++)
                LDSM4(bf[ntp][0], bf[ntp][1], bf[ntp][2], bf[ntp][3],
                      bb + ntp*2304 + ks*32);
            #pragma unroll
            for (int mt = 0; mt < 2; mt++)
                #pragma unroll
                for (int nt = 0; nt < 8; nt++)
                    mma1688(acc[mt][nt], af[mt],
                            bf[nt >> 1][(nt & 1)*2], bf[nt >> 1][(nt & 1)*2 + 1]);
        }
        __syncthreads();
        if (kt + 2 < 8) { load_tile(kt + 2, buf); CP_COMMIT(); }
    }

    // ---------------- epilogue ----------------
    const int m_wbase = m0 + wm*32;
    const int rip  = lane >> 2;                 // row-in-point (0..7), +8 for c2/c3
    const int colb = (lane & 3)*2;

    #pragma unroll
    for (int mt = 0; mt < 2; mt++) {
        const int gmb = m_wbase + mt*16;        // 16-row tile == one point
        const int pt  = gmb >> 4;

        if (EPI == 0) {
            const int bq  = pt >> 12;
            const int nb0 = g_idx[pt*16 + rip];
            const int nb1 = g_idx[pt*16 + rip + 8];
            const size_t qb  = (size_t)pt*256;
            const size_t kb0 = ((size_t)(bq << 12) + nb0)*256;
            const size_t kb1 = ((size_t)(bq << 12) + nb1)*256;
            const size_t tr0 = (size_t)(gmb + rip)*256;
            const size_t tr1 = tr0 + 8*256;
            #pragma unroll
            for (int nt = 0; nt < 8; nt++) {
                int col = n0 + wn*64 + nt*8 + colb;
                float2 q  = *(const float2*)&g_Q [qb  + col];
                float2 ka = *(const float2*)&g_Kf[kb0 + col];
                float2 kb = *(const float2*)&g_Kf[kb1 + col];
                float2 va = *(const float2*)&g_Vf[kb0 + col];
                float2 vb = *(const float2*)&g_Vf[kb1 + col];
                float p00 = acc[mt][nt][0], p01 = acc[mt][nt][1];
                float p10 = acc[mt][nt][2], p11 = acc[mt][nt][3];
                *(float2*)&g_t[tr0 + col] = make_float2(rna_tf32(q.x - ka.x + p00),
                                                        rna_tf32(q.y - ka.y + p01));
                *(float2*)&g_t[tr1 + col] = make_float2(rna_tf32(q.x - kb.x + p10),
                                                        rna_tf32(q.y - kb.y + p11));
                *(float2*)&g_U[tr0 + col] = make_float2(va.x + p00, va.y + p01);
                *(float2*)&g_U[tr1 + col] = make_float2(vb.x + p10, vb.y + p11);
            }
        } else if (EPI == 1) {
            const size_t tr0 = (size_t)(gmb + rip)*256;
            const size_t tr1 = tr0 + 8*256;
            #pragma unroll
            for (int nt = 0; nt < 8; nt++) {
                int col = n0 + wn*64 + nt*8 + colb;
                *(float2*)&g_h1[tr0 + col] = make_float2(
                    rna_tf32(fmaxf(acc[mt][nt][0], 0.f)),
                    rna_tf32(fmaxf(acc[mt][nt][1], 0.f)));
                *(float2*)&g_h1[tr1 + col] = make_float2(
                    rna_tf32(fmaxf(acc[mt][nt][2], 0.f)),
                    rna_tf32(fmaxf(acc[mt][nt][3], 0.f)));
            }
        } else {
            const float sc = 0.0625f;           // 1/sqrt(256)
            const size_t ub0 = (size_t)(gmb + rip)*256;
            const size_t ub1 = ub0 + 8*256;
            #pragma unroll
            for (int nt = 0; nt < 8; nt++) {
                int col = n0 + wn*64 + nt*8 + colb;
                float2 u0 = *(const float2*)&g_U[ub0 + col];
                float2 u1 = *(const float2*)&g_U[ub1 + col];
                float rout[2];
                #pragma unroll
                for (int p = 0; p < 2; p++) {
                    float x0 = acc[mt][nt][p]     * sc;
                    float x1 = acc[mt][nt][2 + p] * sc;
                    float mx = fmaxf(x0, x1);
                    #pragma unroll
                    for (int o = 4; o < 32; o <<= 1)
                        mx = fmaxf(mx, __shfl_xor_sync(0xffffffffu, mx, o));
                    float e0 = __expf(x0 - mx), e1 = __expf(x1 - mx);
                    float uu0 = p ? u0.y : u0.x;
                    float uu1 = p ? u1.y : u1.x;
                    float s = e0 + e1;
                    float w = e0*uu0 + e1*uu1;
                    #pragma unroll
                    for (int o = 4; o < 32; o <<= 1) {
                        s += __shfl_xor_sync(0xffffffffu, s, o);
                        w += __shfl_xor_sync(0xffffffffu, w, o);
                    }
                    rout[p] = w / s;
                }
                if (lane < 4)
                    *(float2*)&g_res[(size_t)pt*256 + col] = make_float2(rout[0], rout[1]);
            }
        }
    }
}

// ---------------- final: proj + LN + post + LN + residual (16 pts / block) -------
__global__ void __launch_bounds__(256) final_kernel(
    const float* __restrict__ features, const float* __restrict__ b_post,
    const float* __restrict__ gdm, const float* __restrict__ bdm,
    const float* __restrict__ gdp, const float* __restrict__ bdp,
    float* __restrict__ out)
{
    int p0 = blockIdx.x * 16;
    int f  = threadIdx.x;
    __shared__ __align__(16) float rstage[DM*20];
    __shared__ float obuf[16*260];

    #pragma unroll
    for (int i = 0; i < 16; i++)
        rstage[f*20 + i] = g_res[(size_t)(p0 + i)*DM + f];
    __syncthreads();

    float acc[16];
    #pragma unroll
    for (int k = 0; k < 16; k++) acc[k] = 0.f;
    gemv16<DM>(g_WprojT, rstage, f, acc);
    #pragma unroll
    for (int k = 0; k < 16; k++) obuf[k*260 + f] = acc[k];
    __syncthreads();

    int wid = f >> 5, lane = f & 31;
    #pragma unroll
    for (int pp = 0; pp < 2; pp++) {
        int p = wid*2 + pp;
        const float* row = &obuf[p*260];
        float v[8]; float s = 0.f, s2 = 0.f;
        #pragma unroll
        for (int i = 0; i < 8; i++) { float x = row[lane*8 + i]; v[i] = x; s += x; s2 += x*x; }
        warp_bfly2(s, s2);
        float mu  = s  * (1.f/DM);
        float var = s2 * (1.f/DM) - mu*mu;
        float rs  = rsqrtf(var + 1e-5f);
        #pragma unroll
        for (int i = 0; i < 8; i++) {
            int c = lane*8 + i;
            rstage[c*20 + p] = (v[i] - mu) * rs * gdm[c] + bdm[c];
        }
    }
    __syncthreads();

    int po = f & 63, pg = f >> 6;
    float a4x = b_post[po], a4y = a4x, a4z = a4x, a4w = a4x;
    #pragma unroll 4
    for (int j = 0; j < DM; j++) {
        float w = __ldg(&g_WpostT[j*DP + po]);
        float4 z4 = *reinterpret_cast<const float4*>(&rstage[j*20 + pg*4]);
        a4x = fmaf(w, z4.x, a4x); a4y = fmaf(w, z4.y, a4y);
        a4z = fmaf(w, z4.z, a4z); a4w = fmaf(w, z4.w, a4w);
    }
    __syncthreads();
    obuf[(pg*4 + 0)*68 + po] = a4x;
    obuf[(pg*4 + 1)*68 + po] = a4y;
    obuf[(pg*4 + 2)*68 + po] = a4z;
    obuf[(pg*4 + 3)*68 + po] = a4w;
    __syncthreads();

    #pragma unroll
    for (int pp = 0; pp < 2; pp++) {
        int p = wid*2 + pp;
        float x0 = obuf[p*68 + lane], x1 = obuf[p*68 + 32 + lane];
        float s = x0 + x1, s2 = x0*x0 + x1*x1;
        warp_bfly2(s, s2);
        float mu  = s  * (1.f/DP);
        float var = s2 * (1.f/DP) - mu*mu;
        float rs  = rsqrtf(var + 1e-5f);
        size_t base = (size_t)(p0 + p)*DP;
        out[base + lane]      = (x0 - mu)*rs*gdp[lane]      + bdp[lane]      + features[base + lane];
        out[base + 32 + lane] = (x1 - mu)*rs*gdp[32 + lane] + bdp[32 + lane] + features[base + 32 + lane];
    }
}

// ---------------- gemm A-source trampolines (device symbols, no host lookup) ----
__global__ void __launch_bounds__(256) gemm_pos_launcher();  // unused

// ---------------- launch ----------------
extern "C" void kernel_launch(void* const* d_in, const int* in_sizes, int n_in,
                              void* d_out, int out_size)
{
    const float* xyz      = (const float*)d_in[0];
    const float* features = (const float*)d_in[1];
    const float* W_pre    = (const float*)d_in[2];
    const float* b_pre    = (const float*)d_in[3];
    const float* W_post   = (const float*)d_in[4];
    const float* b_post   = (const float*)d_in[5];
    const float* Wp1      = (const float*)d_in[6];
    const float* Wp2      = (const float*)d_in[7];
    const float* Wa1      = (const float*)d_in[8];
    const float* Wa2      = (const float*)d_in[9];
    const float* WQ       = (const float*)d_in[10];
    const float* WK       = (const float*)d_in[11];
    const float* WV       = (const float*)d_in[12];
    const float* Wproj    = (const float*)d_in[13];
    const float* g_dm     = (const float*)d_in[14];
    const float* b_dm     = (const float*)d_in[15];
    const float* g_dp     = (const float*)d_in[16];
    const float* b_dp     = (const float*)d_in[17];
    float* out = (float*)d_out;

    // resolve device pointers for GEMM operands (no allocation, capture-safe)
    float *d_h1, *d_t, *d_Wp2r, *d_Wa1r, *d_Wa2r;
    cudaGetSymbolAddress((void**)&d_h1,   g_h1);
    cudaGetSymbolAddress((void**)&d_t,    g_t);
    cudaGetSymbolAddress((void**)&d_Wp2r, g_Wp2r);
    cudaGetSymbolAddress((void**)&d_Wa1r, g_Wa1r);
    cudaGetSymbolAddress((void**)&d_Wa2r, g_Wa2r);

    cudaFuncSetAttribute(knn_kernel, cudaFuncAttributeMaxDynamicSharedMemorySize,
                         NN * (int)sizeof(float4));
    cudaFuncSetAttribute(gemm_kernel<0>, cudaFuncAttributeMaxDynamicSharedMemorySize, GEMM_SMEM);
    cudaFuncSetAttribute(gemm_kernel<1>, cudaFuncAttributeMaxDynamicSharedMemorySize, GEMM_SMEM);
    cudaFuncSetAttribute(gemm_kernel<2>, cudaFuncAttributeMaxDynamicSharedMemorySize, GEMM_SMEM);

    prep_kernel<<<256, 256>>>(W_pre, WQ, WK, WV, Wproj, W_post, Wp2, Wa1, Wa2);
    knn_kernel<<<BB*(NN/256), 256, NN*sizeof(float4)>>>(xyz);
    qkv_kernel<<<NPTS/16, 256>>>(features, b_pre, g_dm, b_dm);
    h1_kernel<<<NPTS, 256>>>(xyz, Wp1);

    dim3 ggrid(MTOT/128, 2);
    gemm_kernel<0><<<ggrid, 256, GEMM_SMEM>>>(d_h1, d_Wp2r);  // pos -> t, U
    gemm_kernel<1><<<ggrid, 256, GEMM_SMEM>>>(d_t,  d_Wa1r);  // h2 = relu
    gemm_kernel<2><<<ggrid, 256, GEMM_SMEM>>>(d_h1, d_Wa2r);  // attn -> softmax -> res

    final_kernel<<<NPTS/16, 256>>>(features, b_post, g_dm, b_dm, g_dp, b_dp, out);
}